// round 1
// baseline (speedup 1.0000x reference)
#include <cuda_runtime.h>
#include <math.h>

// DeconvDft2dLayer: reduces exactly to per-row (W=512) circular convolution.
// y[row,:] = ifft( M(k) * fft(x[row,:]) ),  M(k) = 1/|H(k)|^4 (real),
// H(k) = sum_{n=0}^{7} w[n] e^{-2pi i k n / 512}.
// Two real rows packed as one complex FFT (M real => trick is exact).

#define NW 512
#define NTHREADS 128

__device__ float d_M[NW];  // M(k) / 512  (ifft normalization folded in)

__global__ void compute_M_kernel(const float* __restrict__ w) {
    int k = threadIdx.x;
    if (k < NW) {
        double hr = 0.0, hi = 0.0;
        for (int n = 0; n < 8; n++) {
            double ang = -2.0 * M_PI * (double)(k * n) / (double)NW;
            hr += (double)w[n] * cos(ang);
            hi += (double)w[n] * sin(ang);
        }
        double p = hr * hr + hi * hi;      // |H|^2
        d_M[k] = (float)(1.0 / (p * p) / (double)NW);
    }
}

__device__ __forceinline__ float2 cmul(float2 a, float2 b) {
    return make_float2(a.x * b.x - a.y * b.y, a.x * b.y + a.y * b.x);
}

// One Stockham radix-4 stage: N = current sub-transform size, S = stride.
// N*S == 512. 128 butterflies total -> one per thread.
// X,Y are 512-entry float2 shared buffers. tw[j] = exp(-2pi i j/512), j in [0,512).
template<int N, int S>
__device__ __forceinline__ void stage_r4(const float2* __restrict__ X,
                                         float2* __restrict__ Y,
                                         const float2* __restrict__ tw,
                                         int tid, bool inv) {
    constexpr int TW = NW / N;
    int p = tid / S;
    int q = tid - p * S;

    float2 a = X[tid];          // q + S*p
    float2 b = X[tid + 128];    // q + S*(p +   N/4)   (S*N/4 == 128)
    float2 c = X[tid + 256];
    float2 d = X[tid + 384];

    float2 w1 = tw[p * TW];
    float2 w2 = tw[2 * p * TW];
    float2 w3 = tw[3 * p * TW];
    if (inv) { w1.y = -w1.y; w2.y = -w2.y; w3.y = -w3.y; }

    float2 apc = make_float2(a.x + c.x, a.y + c.y);
    float2 amc = make_float2(a.x - c.x, a.y - c.y);
    float2 bpd = make_float2(b.x + d.x, b.y + d.y);
    float2 bmd = make_float2(b.x - d.x, b.y - d.y);
    float2 jb  = make_float2(-bmd.y, bmd.x);   // j*(b-d)

    float e = inv ? 1.0f : -1.0f;
    float2 t1 = make_float2(amc.x + e * jb.x, amc.y + e * jb.y);
    float2 t3 = make_float2(amc.x - e * jb.x, amc.y - e * jb.y);
    float2 t2 = make_float2(apc.x - bpd.x, apc.y - bpd.y);

    int base = tid + 3 * S * p;   // q + 4*S*p
    Y[base]         = make_float2(apc.x + bpd.x, apc.y + bpd.y);
    Y[base + S]     = cmul(w1, t1);
    Y[base + 2 * S] = cmul(w2, t2);
    Y[base + 3 * S] = cmul(w3, t3);
}

// Final radix-2 stage: N=2, S=256. 256 butterflies, 2 per thread. No twiddle.
__device__ __forceinline__ void stage_r2_final(const float2* __restrict__ X,
                                               float2* __restrict__ Y, int tid) {
#pragma unroll
    for (int i = 0; i < 2; i++) {
        int q = tid + i * 128;
        float2 a = X[q];
        float2 b = X[q + 256];
        Y[q]       = make_float2(a.x + b.x, a.y + b.y);
        Y[q + 256] = make_float2(a.x - b.x, a.y - b.y);
    }
}

__global__ void __launch_bounds__(NTHREADS)
fft_conv_kernel(const float* __restrict__ x, float* __restrict__ out) {
    __shared__ float2 bufA[NW];
    __shared__ float2 bufB[NW];
    __shared__ float2 tw[NW];

    int tid = threadIdx.x;
    long long row0 = (long long)blockIdx.x * 2;
    const float* x0 = x + row0 * NW;
    const float* x1 = x0 + NW;
    float* o0 = out + row0 * NW;
    float* o1 = o0 + NW;

    // Twiddle table: exp(-2pi i j / 512)
#pragma unroll
    for (int j = tid; j < NW; j += NTHREADS) {
        float s, c;
        sincospif(2.0f * (float)j / (float)NW, &s, &c);
        tw[j] = make_float2(c, -s);
    }
    // Pack two real rows into one complex sequence.
#pragma unroll
    for (int i = tid; i < NW; i += NTHREADS) {
        bufA[i] = make_float2(x0[i], x1[i]);
    }
    __syncthreads();

    // ---- forward FFT: A -> B -> A -> B -> A -> B ----
    stage_r4<512, 1 >(bufA, bufB, tw, tid, false); __syncthreads();
    stage_r4<128, 4 >(bufB, bufA, tw, tid, false); __syncthreads();
    stage_r4< 32, 16>(bufA, bufB, tw, tid, false); __syncthreads();
    stage_r4<  8, 64>(bufB, bufA, tw, tid, false); __syncthreads();
    stage_r2_final(bufA, bufB, tid);               __syncthreads();

    // ---- pointwise multiply by real M(k)/512 (in-place in B) ----
#pragma unroll
    for (int k = tid; k < NW; k += NTHREADS) {
        float m = d_M[k];
        bufB[k].x *= m;
        bufB[k].y *= m;
    }
    __syncthreads();

    // ---- inverse FFT: B -> A -> B -> A -> B -> A ----
    stage_r4<512, 1 >(bufB, bufA, tw, tid, true); __syncthreads();
    stage_r4<128, 4 >(bufA, bufB, tw, tid, true); __syncthreads();
    stage_r4< 32, 16>(bufB, bufA, tw, tid, true); __syncthreads();
    stage_r4<  8, 64>(bufA, bufB, tw, tid, true); __syncthreads();
    stage_r2_final(bufB, bufA, tid);              __syncthreads();

    // Unpack: real -> row0, imag -> row1. (1/512 already folded into M.)
#pragma unroll
    for (int i = tid; i < NW; i += NTHREADS) {
        float2 v = bufA[i];
        o0[i] = v.x;
        o1[i] = v.y;
    }
}

extern "C" void kernel_launch(void* const* d_in, const int* in_sizes, int n_in,
                              void* d_out, int out_size) {
    const float* x = (const float*)d_in[0];
    const float* w = (const float*)d_in[1];
    if (n_in >= 2 && in_sizes[0] < in_sizes[1]) {  // defensive: x is the big one
        const float* t = x; x = w; w = t;
    }
    float* out = (float*)d_out;

    compute_M_kernel<<<1, NW>>>(w);

    int rows = out_size / NW;        // 16384
    int blocks = rows / 2;           // 8192 (two rows per block)
    fft_conv_kernel<<<blocks, NTHREADS>>>(x, out);
}

// round 2
// speedup vs baseline: 3.3235x; 3.3235x over previous
#include <cuda_runtime.h>

// DeconvDft2dLayer == per-row 512-pt circular deconvolution:
//   y[row,:] = ifft( M(k) * fft(x[row,:]) ),  M(k) = 1/|H(k)|^4 (real),
//   H(k) = sum_{n=0}^{7} w[n] e^{-2pi i k n/512}.
// Two real rows packed into one complex FFT (valid since M is real).
// Radix-8 Stockham (3 stages/direction), register-resident butterflies,
// gmem-fused first/last stages, spectrum multiply fused in registers.

#define NW 512
#define TPF 64                    // threads per FFT (one row-pair)
#define NF  4                     // FFTs per block (8 rows)
#define THREADS (TPF * NF)        // 256
#define PADLEN (NW + (NW >> 3))   // 576 floats, pad 1 per 8

__device__ float d_M[NW];         // M(k)/512  (ifft 1/N folded in)

__global__ void compute_M_kernel(const float* __restrict__ w) {
    int k = threadIdx.x;
    float hr = 0.0f, hi = 0.0f;
#pragma unroll
    for (int n = 0; n < 8; n++) {
        int t = (k * n) & (NW - 1);          // exact integer phase
        float s, c;
        sincospif(-(float)t * (2.0f / NW), &s, &c);   // e^{-2pi i t/512}
        hr = fmaf(w[n], c, hr);
        hi = fmaf(w[n], s, hi);
    }
    float p = hr * hr + hi * hi;             // |H|^2
    d_M[k] = 1.0f / (p * p * (float)NW);
}

__device__ __forceinline__ int IDX(int i) { return i + (i >> 3); }

// In-register radix-8 DFT. Forward: omega8 = e^{-i pi/4}; INV flips sign s.
template<bool INV>
__device__ __forceinline__ void dft8(float* ar, float* ai) {
    const float s = INV ? 1.0f : -1.0f;
    const float C = 0.70710678118654752440f;

    // even DFT4 on (0,2,4,6)
    float e0r = ar[0] + ar[4], e0i = ai[0] + ai[4];
    float e1r = ar[0] - ar[4], e1i = ai[0] - ai[4];
    float e2r = ar[2] + ar[6], e2i = ai[2] + ai[6];
    float e3r = ar[2] - ar[6], e3i = ai[2] - ai[6];
    float E0r = e0r + e2r, E0i = e0i + e2i;
    float E2r = e0r - e2r, E2i = e0i - e2i;
    float E1r = e1r - s * e3i, E1i = e1i + s * e3r;   // t1 + s*i*t3
    float E3r = e1r + s * e3i, E3i = e1i - s * e3r;

    // odd DFT4 on (1,3,5,7)
    float o0r = ar[1] + ar[5], o0i = ai[1] + ai[5];
    float o1r = ar[1] - ar[5], o1i = ai[1] - ai[5];
    float o2r = ar[3] + ar[7], o2i = ai[3] + ai[7];
    float o3r = ar[3] - ar[7], o3i = ai[3] - ai[7];
    float O0r = o0r + o2r, O0i = o0i + o2i;
    float O2r = o0r - o2r, O2i = o0i - o2i;
    float O1r = o1r - s * o3i, O1i = o1i + s * o3r;
    float O3r = o1r + s * o3i, O3i = o1i - s * o3r;

    // combine: b_j = E_j + w8^j O_j ; b_{j+4} = E_j - w8^j O_j
    // w8^1 = C*(1 + s*i); w8^2 = s*i; w8^3 = C*(-1 + s*i)
    float w1r = C * (O1r - s * O1i), w1i = C * (s * O1r + O1i);
    float w2r = -s * O2i,            w2i = s * O2r;
    float w3r = C * (-O3r - s * O3i), w3i = C * (s * O3r - O3i);

    ar[0] = E0r + O0r; ai[0] = E0i + O0i;
    ar[4] = E0r - O0r; ai[4] = E0i - O0i;
    ar[1] = E1r + w1r; ai[1] = E1i + w1i;
    ar[5] = E1r - w1r; ai[5] = E1i - w1i;
    ar[2] = E2r + w2r; ai[2] = E2i + w2i;
    ar[6] = E2r - w2r; ai[6] = E2i - w2i;
    ar[3] = E3r + w3r; ai[3] = E3i + w3i;
    ar[7] = E3r - w3r; ai[7] = E3i - w3i;
}

// Multiply b_j by W^j (W conjugated for inverse) and store to padded smem at
// base + stride*j. Powers built by a register cmul chain (one table load).
template<bool INV>
__device__ __forceinline__ void tw_store(float* __restrict__ br, float* __restrict__ bi,
                                         const float* ar, const float* ai,
                                         float2 W, int base, int stride) {
    if (INV) W.y = -W.y;
    br[IDX(base)] = ar[0];
    bi[IDX(base)] = ai[0];
    float cr = W.x, ci = W.y;
#pragma unroll
    for (int j = 1; j < 8; j++) {
        br[IDX(base + stride * j)] = ar[j] * cr - ai[j] * ci;
        bi[IDX(base + stride * j)] = ar[j] * ci + ai[j] * cr;
        float nr = cr * W.x - ci * W.y;
        float ni = cr * W.y + ci * W.x;
        cr = nr; ci = ni;
    }
}

__device__ __forceinline__ void loadS(float* ar, float* ai,
                                      const float* __restrict__ br,
                                      const float* __restrict__ bi, int u) {
#pragma unroll
    for (int j = 0; j < 8; j++) {
        ar[j] = br[IDX(u + 64 * j)];
        ai[j] = bi[IDX(u + 64 * j)];
    }
}

__global__ void __launch_bounds__(THREADS, 4)
fft_conv_kernel(const float* __restrict__ x, float* __restrict__ out) {
    __shared__ float sAr[NF][PADLEN], sAi[NF][PADLEN];
    __shared__ float sBr[NF][PADLEN], sBi[NF][PADLEN];
    __shared__ float2 tw[NW];

    int tid = threadIdx.x;
    int f = tid >> 6;        // which FFT in block
    int u = tid & 63;        // lane within FFT

    // twiddle table: tw[j] = e^{-2pi i j / 512}
    for (int j = tid; j < NW; j += THREADS) {
        float s, c;
        sincospif(-(float)j * (2.0f / NW), &s, &c);
        tw[j] = make_float2(c, s);
    }

    long long row0 = ((long long)blockIdx.x * NF + f) * 2;
    const float* x0 = x + row0 * NW;
    const float* x1 = x0 + NW;

    float ar[8], ai[8];
#pragma unroll
    for (int j = 0; j < 8; j++) {          // pack two real rows as complex
        ar[j] = x0[u + 64 * j];
        ai[j] = x1[u + 64 * j];
    }
    __syncthreads();                       // tw ready

    // ---- forward ----
    // stage 1: (N=512,S=1)  p=u, W=tw[u], out[8u+j]
    dft8<false>(ar, ai);
    tw_store<false>(sBr[f], sBi[f], ar, ai, tw[u], 8 * u, 1);
    __syncthreads();

    // stage 2: (N=64,S=8)   p=u>>3, q=u&7, W=tw[8p], out[q+64p+8j]
    loadS(ar, ai, sBr[f], sBi[f], u);
    dft8<false>(ar, ai);
    {
        int p = u >> 3, q = u & 7;
        tw_store<false>(sAr[f], sAi[f], ar, ai, tw[8 * p], q + 64 * p, 8);
    }
    __syncthreads();

    // stage 3: (N=8,S=64) no twiddle; output natural index u+64j — exactly the
    // inverse stage-1 input layout, so fuse: multiply by M and run inverse
    // stage 1 without touching shared memory.
    loadS(ar, ai, sAr[f], sAi[f], u);
    dft8<false>(ar, ai);
#pragma unroll
    for (int j = 0; j < 8; j++) {
        float m = d_M[u + 64 * j];
        ar[j] *= m;
        ai[j] *= m;
    }

    // ---- inverse ----
    dft8<true>(ar, ai);
    tw_store<true>(sBr[f], sBi[f], ar, ai, tw[u], 8 * u, 1);
    __syncthreads();

    loadS(ar, ai, sBr[f], sBi[f], u);
    dft8<true>(ar, ai);
    {
        int p = u >> 3, q = u & 7;
        tw_store<true>(sAr[f], sAi[f], ar, ai, tw[8 * p], q + 64 * p, 8);
    }
    __syncthreads();

    loadS(ar, ai, sAr[f], sAi[f], u);
    dft8<true>(ar, ai);

    float* o0 = out + row0 * NW;
    float* o1 = o0 + NW;
#pragma unroll
    for (int j = 0; j < 8; j++) {          // unpack: real->row0, imag->row1
        o0[u + 64 * j] = ar[j];
        o1[u + 64 * j] = ai[j];
    }
}

extern "C" void kernel_launch(void* const* d_in, const int* in_sizes, int n_in,
                              void* d_out, int out_size) {
    const float* x = (const float*)d_in[0];
    const float* w = (const float*)d_in[1];
    if (n_in >= 2 && in_sizes[0] < in_sizes[1]) {   // defensive: x is the big one
        const float* t = x; x = w; w = t;
    }
    float* out = (float*)d_out;

    compute_M_kernel<<<1, NW>>>(w);

    int rows = out_size / NW;          // 16384
    int blocks = rows / (2 * NF);      // 2048
    fft_conv_kernel<<<blocks, THREADS>>>(x, out);
}

// round 3
// speedup vs baseline: 4.2156x; 1.2684x over previous
#include <cuda_runtime.h>

// DeconvDft2dLayer == per-row 512-pt circular deconvolution:
//   y[row,:] = ifft( M(k) * fft(x[row,:]) ),  M(k) = 1/|H(k)|^4 (real),
//   H(k) = sum_{n=0}^{7} w[n] e^{-2pi i k n/512}.
// Two real rows packed into one complex FFT (valid: M is real).
// Radix-8 Stockham, register butterflies, float2 smem exchanges with
// pad-per-8 swizzle, computed twiddles (log-depth power chains),
// per-FFT named barriers (no block-wide syncs).

#define NW 512
#define TPF 64
#define NF  4
#define THREADS (TPF * NF)      // 256
#define PAD2 (NW + (NW >> 3))   // 576 float2 per buffer

__device__ float d_M[NW];       // M(k)/512  (ifft 1/N folded in)

__global__ void compute_M_kernel(const float* __restrict__ w) {
    int k = threadIdx.x;
    float hr = 0.0f, hi = 0.0f;
#pragma unroll
    for (int n = 0; n < 8; n++) {
        int t = (k * n) & (NW - 1);
        float s, c;
        sincospif(-(float)t * (2.0f / NW), &s, &c);
        hr = fmaf(w[n], c, hr);
        hi = fmaf(w[n], s, hi);
    }
    float p = hr * hr + hi * hi;
    d_M[k] = 1.0f / (p * p * (float)NW);
}

__device__ __forceinline__ float2 cmulf(float2 a, float2 b) {
    return make_float2(a.x * b.x - a.y * b.y, a.x * b.y + a.y * b.x);
}

// In-register radix-8 DFT. Forward uses e^{-i...}; INV flips sign.
template<bool INV>
__device__ __forceinline__ void dft8(float* ar, float* ai) {
    const float s = INV ? 1.0f : -1.0f;
    const float C = 0.70710678118654752440f;

    float e0r = ar[0] + ar[4], e0i = ai[0] + ai[4];
    float e1r = ar[0] - ar[4], e1i = ai[0] - ai[4];
    float e2r = ar[2] + ar[6], e2i = ai[2] + ai[6];
    float e3r = ar[2] - ar[6], e3i = ai[2] - ai[6];
    float E0r = e0r + e2r, E0i = e0i + e2i;
    float E2r = e0r - e2r, E2i = e0i - e2i;
    float E1r = e1r - s * e3i, E1i = e1i + s * e3r;
    float E3r = e1r + s * e3i, E3i = e1i - s * e3r;

    float o0r = ar[1] + ar[5], o0i = ai[1] + ai[5];
    float o1r = ar[1] - ar[5], o1i = ai[1] - ai[5];
    float o2r = ar[3] + ar[7], o2i = ai[3] + ai[7];
    float o3r = ar[3] - ar[7], o3i = ai[3] - ai[7];
    float O0r = o0r + o2r, O0i = o0i + o2i;
    float O2r = o0r - o2r, O2i = o0i - o2i;
    float O1r = o1r - s * o3i, O1i = o1i + s * o3r;
    float O3r = o1r + s * o3i, O3i = o1i - s * o3r;

    float w1r = C * (O1r - s * O1i), w1i = C * (s * O1r + O1i);
    float w2r = -s * O2i,             w2i = s * O2r;
    float w3r = C * (-O3r - s * O3i), w3i = C * (s * O3r - O3i);

    ar[0] = E0r + O0r; ai[0] = E0i + O0i;
    ar[4] = E0r - O0r; ai[4] = E0i - O0i;
    ar[1] = E1r + w1r; ai[1] = E1i + w1i;
    ar[5] = E1r - w1r; ai[5] = E1i - w1i;
    ar[2] = E2r + w2r; ai[2] = E2i + w2i;
    ar[6] = E2r - w2r; ai[6] = E2i - w2i;
    ar[3] = E3r + w3r; ai[3] = E3i + w3i;
    ar[7] = E3r - w3r; ai[7] = E3i - w3i;
}

// Twiddle by W^j (conjugated for INV) and store float2 at base + stride*j
// (indices already in padded space). Powers: log-depth chain, depth 3.
template<bool INV>
__device__ __forceinline__ void tw_store_v(float2* __restrict__ buf,
                                           const float* ar, const float* ai,
                                           float2 w, int base, int stride) {
    buf[base] = make_float2(ar[0], ai[0]);
    float2 c2 = cmulf(w, w);
    float2 c3 = cmulf(c2, w);
    float2 c4 = cmulf(c2, c2);
    float2 c5 = cmulf(c4, w);
    float2 c6 = cmulf(c4, c2);
    float2 c7 = cmulf(c4, c3);
    float2 cs[8];
    cs[1] = w; cs[2] = c2; cs[3] = c3; cs[4] = c4; cs[5] = c5; cs[6] = c6; cs[7] = c7;
#pragma unroll
    for (int j = 1; j < 8; j++) {
        float cr = cs[j].x;
        float ci = INV ? -cs[j].y : cs[j].y;
        buf[base + stride * j] =
            make_float2(ar[j] * cr - ai[j] * ci, ar[j] * ci + ai[j] * cr);
    }
}

__device__ __forceinline__ void load_v(float* ar, float* ai,
                                       const float2* __restrict__ buf, int ub) {
#pragma unroll
    for (int j = 0; j < 8; j++) {
        float2 v = buf[ub + 72 * j];
        ar[j] = v.x;
        ai[j] = v.y;
    }
}

#define FFT_BAR(fid) asm volatile("bar.sync %0, %1;" :: "r"((fid) + 1), "r"(64) : "memory")

__global__ void __launch_bounds__(THREADS, 5)
fft_conv_kernel(const float* __restrict__ x, float* __restrict__ out) {
    __shared__ float2 sA[NF][PAD2];
    __shared__ float2 sB[NF][PAD2];

    int tid = threadIdx.x;
    int f = tid >> 6;
    int u = tid & 63;
    int ub = u + (u >> 3);
    int p = u >> 3, q = u & 7;

    // Per-thread twiddle bases (inverse = conjugate, free at use).
    float2 w1, w2;
    sincospif(-(float)u * (1.0f / 256.0f), &w1.y, &w1.x);   // e^{-2pi i u/512}
    sincospif(-(float)p * (1.0f / 32.0f),  &w2.y, &w2.x);   // e^{-2pi i p/64}

    long long row0 = ((long long)blockIdx.x * NF + f) * 2;
    const float* x0 = x + row0 * NW;
    const float* x1 = x0 + NW;

    float ar[8], ai[8];
#pragma unroll
    for (int j = 0; j < 8; j++) {
        ar[j] = __ldg(x0 + u + 64 * j);
        ai[j] = __ldg(x1 + u + 64 * j);
    }

    // ---- forward ----
    dft8<false>(ar, ai);
    tw_store_v<false>(sB[f], ar, ai, w1, 9 * u, 1);
    FFT_BAR(f);

    load_v(ar, ai, sB[f], ub);
    dft8<false>(ar, ai);
    tw_store_v<false>(sA[f], ar, ai, w2, q + 72 * p, 9);
    FFT_BAR(f);

    load_v(ar, ai, sA[f], ub);
    dft8<false>(ar, ai);                 // natural order: reg j holds bin u+64j

    // ---- spectrum multiply (real M) fused in registers ----
#pragma unroll
    for (int j = 0; j < 8; j++) {
        float m = __ldg(&d_M[u + 64 * j]);
        ar[j] *= m;
        ai[j] *= m;
    }

    // ---- inverse ----
    dft8<true>(ar, ai);
    tw_store_v<true>(sB[f], ar, ai, w1, 9 * u, 1);
    FFT_BAR(f);

    load_v(ar, ai, sB[f], ub);
    dft8<true>(ar, ai);
    tw_store_v<true>(sA[f], ar, ai, w2, q + 72 * p, 9);
    FFT_BAR(f);

    load_v(ar, ai, sA[f], ub);
    dft8<true>(ar, ai);

    float* o0 = out + row0 * NW;
    float* o1 = o0 + NW;
#pragma unroll
    for (int j = 0; j < 8; j++) {
        o0[u + 64 * j] = ar[j];
        o1[u + 64 * j] = ai[j];
    }
}

extern "C" void kernel_launch(void* const* d_in, const int* in_sizes, int n_in,
                              void* d_out, int out_size) {
    const float* x = (const float*)d_in[0];
    const float* w = (const float*)d_in[1];
    if (n_in >= 2 && in_sizes[0] < in_sizes[1]) {
        const float* t = x; x = w; w = t;
    }
    float* out = (float*)d_out;

    compute_M_kernel<<<1, NW>>>(w);

    int rows = out_size / NW;        // 16384
    int blocks = rows / (2 * NF);    // 2048
    fft_conv_kernel<<<blocks, THREADS>>>(x, out);
}

// round 4
// speedup vs baseline: 4.4639x; 1.0589x over previous
#include <cuda_runtime.h>

// DeconvDft2dLayer == per-row 512-pt circular deconvolution:
//   y[row,:] = ifft( M(k) * fft(x[row,:]) ),  M(k) = 1/|H(k)|^4 (real),
//   H(k) = sum_{n=0}^{7} w[n] e^{-2pi i k n/512}.
// Two real rows packed per complex FFT (valid: M real). Each thread runs TWO
// independent complex FFTs (4 rows) for 2x ILP; twiddle chains amortized.
// Radix-8 Stockham, padded conflict-free smem, spectrum multiply in regs.

#define NW 512
#define THREADS 64
#define PAD2 (NW + (NW >> 3))   // 576 float2

__device__ float d_M[NW];        // M(k)/512  (ifft 1/N folded in)

__global__ void compute_M_kernel(const float* __restrict__ w) {
    int k = threadIdx.x;
    float hr = 0.0f, hi = 0.0f;
#pragma unroll
    for (int n = 0; n < 8; n++) {
        int t = (k * n) & (NW - 1);
        float s, c;
        sincospif(-(float)t * (2.0f / NW), &s, &c);
        hr = fmaf(w[n], c, hr);
        hi = fmaf(w[n], s, hi);
    }
    float p = hr * hr + hi * hi;
    d_M[k] = 1.0f / (p * p * (float)NW);
}

__device__ __forceinline__ float2 cmulf(float2 a, float2 b) {
    return make_float2(a.x * b.x - a.y * b.y, a.x * b.y + a.y * b.x);
}

// In-register radix-8 DFT. Forward e^{-i...}; INV flips sign.
template<bool INV>
__device__ __forceinline__ void dft8(float* ar, float* ai) {
    const float s = INV ? 1.0f : -1.0f;
    const float C = 0.70710678118654752440f;

    float e0r = ar[0] + ar[4], e0i = ai[0] + ai[4];
    float e1r = ar[0] - ar[4], e1i = ai[0] - ai[4];
    float e2r = ar[2] + ar[6], e2i = ai[2] + ai[6];
    float e3r = ar[2] - ar[6], e3i = ai[2] - ai[6];
    float E0r = e0r + e2r, E0i = e0i + e2i;
    float E2r = e0r - e2r, E2i = e0i - e2i;
    float E1r = e1r - s * e3i, E1i = e1i + s * e3r;
    float E3r = e1r + s * e3i, E3i = e1i - s * e3r;

    float o0r = ar[1] + ar[5], o0i = ai[1] + ai[5];
    float o1r = ar[1] - ar[5], o1i = ai[1] - ai[5];
    float o2r = ar[3] + ar[7], o2i = ai[3] + ai[7];
    float o3r = ar[3] - ar[7], o3i = ai[3] - ai[7];
    float O0r = o0r + o2r, O0i = o0i + o2i;
    float O2r = o0r - o2r, O2i = o0i - o2i;
    float O1r = o1r - s * o3i, O1i = o1i + s * o3r;
    float O3r = o1r + s * o3i, O3i = o1i - s * o3r;

    float w1r = C * (O1r - s * O1i), w1i = C * (s * O1r + O1i);
    float w2r = -s * O2i,             w2i = s * O2r;
    float w3r = C * (-O3r - s * O3i), w3i = C * (s * O3r - O3i);

    ar[0] = E0r + O0r; ai[0] = E0i + O0i;
    ar[4] = E0r - O0r; ai[4] = E0i - O0i;
    ar[1] = E1r + w1r; ai[1] = E1i + w1i;
    ar[5] = E1r - w1r; ai[5] = E1i - w1i;
    ar[2] = E2r + w2r; ai[2] = E2i + w2i;
    ar[6] = E2r - w2r; ai[6] = E2i - w2i;
    ar[3] = E3r + w3r; ai[3] = E3i + w3i;
    ar[7] = E3r - w3r; ai[7] = E3i - w3i;
}

// Twiddle both batched FFTs by W^j (conj for INV) and store; powers built
// once with a log-depth chain and shared by A and B.
template<bool INV>
__device__ __forceinline__ void tw_store2(float2* __restrict__ bufA,
                                          float2* __restrict__ bufB,
                                          const float* ar, const float* ai,
                                          const float* br, const float* bi,
                                          float2 w, int base, int stride) {
    bufA[base] = make_float2(ar[0], ai[0]);
    bufB[base] = make_float2(br[0], bi[0]);
    float2 cs[8];
    cs[1] = w;
    cs[2] = cmulf(w, w);
    cs[3] = cmulf(cs[2], w);
    cs[4] = cmulf(cs[2], cs[2]);
    cs[5] = cmulf(cs[4], w);
    cs[6] = cmulf(cs[4], cs[2]);
    cs[7] = cmulf(cs[4], cs[3]);
#pragma unroll
    for (int j = 1; j < 8; j++) {
        float cr = cs[j].x;
        float ci = INV ? -cs[j].y : cs[j].y;
        int idx = base + stride * j;
        bufA[idx] = make_float2(ar[j] * cr - ai[j] * ci, ar[j] * ci + ai[j] * cr);
        bufB[idx] = make_float2(br[j] * cr - bi[j] * ci, br[j] * ci + bi[j] * cr);
    }
}

__device__ __forceinline__ void load2(float* ar, float* ai, float* br, float* bi,
                                      const float2* __restrict__ bufA,
                                      const float2* __restrict__ bufB, int ub) {
#pragma unroll
    for (int j = 0; j < 8; j++) {
        float2 va = bufA[ub + 72 * j];
        float2 vb = bufB[ub + 72 * j];
        ar[j] = va.x; ai[j] = va.y;
        br[j] = vb.x; bi[j] = vb.y;
    }
}

__global__ void __launch_bounds__(THREADS, 12)
fft_conv_kernel(const float* __restrict__ x, float* __restrict__ out) {
    __shared__ float2 sP[2][PAD2];   // stage-1 outputs (FFT A, FFT B)
    __shared__ float2 sQ[2][PAD2];   // stage-2 outputs

    int u = threadIdx.x;
    int ub = u + (u >> 3);
    int p = u >> 3, q = u & 7;

    float2 w1, w2;
    sincospif(-(float)u * (1.0f / 256.0f), &w1.y, &w1.x);   // e^{-2pi i u/512}
    sincospif(-(float)p * (1.0f / 32.0f),  &w2.y, &w2.x);   // e^{-2pi i p/64}

    long long row0 = (long long)blockIdx.x * 4;             // 4 rows per block
    const float* xA0 = x + row0 * NW;
    const float* xA1 = xA0 + NW;
    const float* xB0 = xA0 + 2 * NW;
    const float* xB1 = xA0 + 3 * NW;

    float ar[8], ai[8], br[8], bi[8];
#pragma unroll
    for (int j = 0; j < 8; j++) {
        int g = u + 64 * j;
        ar[j] = __ldg(xA0 + g);
        ai[j] = __ldg(xA1 + g);
        br[j] = __ldg(xB0 + g);
        bi[j] = __ldg(xB1 + g);
    }

    // ---- forward ----
    dft8<false>(ar, ai);
    dft8<false>(br, bi);
    tw_store2<false>(sP[0], sP[1], ar, ai, br, bi, w1, 9 * u, 1);
    __syncthreads();

    load2(ar, ai, br, bi, sP[0], sP[1], ub);
    dft8<false>(ar, ai);
    dft8<false>(br, bi);
    tw_store2<false>(sQ[0], sQ[1], ar, ai, br, bi, w2, q + 72 * p, 9);
    __syncthreads();

    load2(ar, ai, br, bi, sQ[0], sQ[1], ub);
    dft8<false>(ar, ai);
    dft8<false>(br, bi);                 // natural order: reg j = bin u+64j

    // ---- spectrum multiply (real M), shared by both FFTs ----
#pragma unroll
    for (int j = 0; j < 8; j++) {
        float m = __ldg(&d_M[u + 64 * j]);
        ar[j] *= m; ai[j] *= m;
        br[j] *= m; bi[j] *= m;
    }

    // ---- inverse ----
    dft8<true>(ar, ai);
    dft8<true>(br, bi);
    tw_store2<true>(sP[0], sP[1], ar, ai, br, bi, w1, 9 * u, 1);
    __syncthreads();

    load2(ar, ai, br, bi, sP[0], sP[1], ub);
    dft8<true>(ar, ai);
    dft8<true>(br, bi);
    tw_store2<true>(sQ[0], sQ[1], ar, ai, br, bi, w2, q + 72 * p, 9);
    __syncthreads();

    load2(ar, ai, br, bi, sQ[0], sQ[1], ub);
    dft8<true>(ar, ai);
    dft8<true>(br, bi);

    float* oA0 = out + row0 * NW;
    float* oA1 = oA0 + NW;
    float* oB0 = oA0 + 2 * NW;
    float* oB1 = oA0 + 3 * NW;
#pragma unroll
    for (int j = 0; j < 8; j++) {
        int g = u + 64 * j;
        oA0[g] = ar[j];
        oA1[g] = ai[j];
        oB0[g] = br[j];
        oB1[g] = bi[j];
    }
}

extern "C" void kernel_launch(void* const* d_in, const int* in_sizes, int n_in,
                              void* d_out, int out_size) {
    const float* x = (const float*)d_in[0];
    const float* w = (const float*)d_in[1];
    if (n_in >= 2 && in_sizes[0] < in_sizes[1]) {
        const float* t = x; x = w; w = t;
    }
    float* out = (float*)d_out;

    compute_M_kernel<<<1, NW>>>(w);

    int rows = out_size / NW;        // 16384
    int blocks = rows / 4;           // 4096 (4 rows per block)
    fft_conv_kernel<<<blocks, THREADS>>>(x, out);
}

// round 5
// speedup vs baseline: 4.6204x; 1.0351x over previous
#include <cuda_runtime.h>

// DeconvDft2dLayer == per-row 512-pt circular deconvolution:
//   y[row,:] = ifft( M(k) * fft(x[row,:]) ),  M(k) = 1/|H(k)|^4 (real),
//   H(k) = sum_{n=0}^{7} w[n] e^{-2pi i k n/512}.
// Two real rows packed per complex FFT (M real => exact).
// 512 = 16 x 32 decomposition: 16 threads/FFT, 32 complex elems/thread,
// ONE smem transpose per direction (vs 2 for radix-8^3), warp-synchronous.
// Inverse via conj trick reuses the identical forward pipeline.

#define NW 512
#define NFB 4                    // FFTs per block
#define THREADS 64               // 16 threads per FFT
#define SROW 17                  // padded row (float2) for conflict-free transpose
#define SBUF (32 * SROW)         // 544 float2 per FFT

__device__ float d_M[NW];        // M(k)/512  (ifft 1/N folded in)

__global__ void compute_M_kernel(const float* __restrict__ w) {
    int k = threadIdx.x;
    float hr = 0.0f, hi = 0.0f;
#pragma unroll
    for (int n = 0; n < 8; n++) {
        int t = (k * n) & (NW - 1);
        float s, c;
        sincospif(-(float)t * (2.0f / NW), &s, &c);
        hr = fmaf(w[n], c, hr);
        hi = fmaf(w[n], s, hi);
    }
    float p = hr * hr + hi * hi;
    d_M[k] = 1.0f / (p * p * (float)NW);
}

// 32nd roots of unity: cos/sin(2*pi*j/32), j = 0..15 (compile-time switch).
__device__ __forceinline__ constexpr float c32(int j) {
    switch (j) {
        case 0:  return 1.0f;
        case 1:  return 0.9807852804032304491f;
        case 2:  return 0.9238795325112867561f;
        case 3:  return 0.8314696123025452371f;
        case 4:  return 0.7071067811865475244f;
        case 5:  return 0.5555702330196022248f;
        case 6:  return 0.3826834323650897717f;
        case 7:  return 0.1950903220161282678f;
        case 8:  return 0.0f;
        case 9:  return -0.1950903220161282678f;
        case 10: return -0.3826834323650897717f;
        case 11: return -0.5555702330196022248f;
        case 12: return -0.7071067811865475244f;
        case 13: return -0.8314696123025452371f;
        case 14: return -0.9238795325112867561f;
        default: return -0.9807852804032304491f;
    }
}
__device__ __forceinline__ constexpr float s32(int j) {
    switch (j) {
        case 0:  return 0.0f;
        case 1:  return 0.1950903220161282678f;
        case 2:  return 0.3826834323650897717f;
        case 3:  return 0.5555702330196022248f;
        case 4:  return 0.7071067811865475244f;
        case 5:  return 0.8314696123025452371f;
        case 6:  return 0.9238795325112867561f;
        case 7:  return 0.9807852804032304491f;
        case 8:  return 1.0f;
        case 9:  return 0.9807852804032304491f;
        case 10: return 0.9238795325112867561f;
        case 11: return 0.8314696123025452371f;
        case 12: return 0.7071067811865475244f;
        case 13: return 0.5555702330196022248f;
        case 14: return 0.3826834323650897717f;
        default: return 0.1950903220161282678f;
    }
}

__device__ __forceinline__ constexpr int brev(int p, int nb) {
    int r = 0;
    for (int i = 0; i < nb; i++) { r = (r << 1) | (p & 1); p >>= 1; }
    return r;
}

// Fully-unrolled radix-2 DIF FFT, size N (<=32). Natural-order input;
// output bit-reversed: x[p] = X[brev(p, log2 N)]. Forward kernel e^{-i...}.
template<int N>
__device__ __forceinline__ void fft_dif(float* __restrict__ xr,
                                        float* __restrict__ xi) {
#pragma unroll
    for (int m = N / 2; m >= 1; m >>= 1) {
#pragma unroll
        for (int g = 0; g < N; g += 2 * m) {
#pragma unroll
            for (int j = 0; j < m; j++) {
                int a = g + j, b = g + j + m;
                float ur = xr[a], ui = xi[a];
                float vr = xr[b], vi = xi[b];
                xr[a] = ur + vr;
                xi[a] = ui + vi;
                float dr = ur - vr, di = ui - vi;
                float wc = c32(j * 16 / m);   // W_{2m}^j = e^{-2pi i j/(2m)}
                float ws = s32(j * 16 / m);
                xr[b] = dr * wc + di * ws;    // (dr+i di)*(wc - i ws)
                xi[b] = di * wc - dr * ws;
            }
        }
    }
}

__global__ void __launch_bounds__(THREADS)
fft_conv_kernel(const float* __restrict__ x, float* __restrict__ out) {
    __shared__ float2 sX[NFB][SBUF];
    __shared__ float sM[NW];

    int tid = threadIdx.x;
    int f = tid >> 4;       // FFT within block
    int t = tid & 15;       // lane within FFT (n1 mod 16 / k2)
    float2* S = sX[f];

    // Block-wide M preload (only block-level sync in the kernel).
#pragma unroll
    for (int i = tid; i < NW; i += THREADS) sM[i] = d_M[i];

    long long row0 = ((long long)blockIdx.x * NFB + f) * 2;
    const float* x0 = x + row0 * NW;
    const float* x1 = x0 + NW;

    // Twiddle bases: b0 = W^t, b1 = W^{t+16}, W = e^{-2pi i/512}.
    float b0r, b0i;
    sincospif(-(float)t * (1.0f / 256.0f), &b0i, &b0r);
    const float wsr = 0.9807852804032304491f;   // cos(pi/16)
    const float wsi = -0.1950903220161282678f;  // -sin(pi/16): e^{-2pi i 16/512}
    float b1r = b0r * wsr - b0i * wsi;
    float b1i = b0r * wsi + b0i * wsr;

    // Load: group b holds x[n], n = t + 16b + 32*n2 (n2 natural).
    float ar[2][16], ai[2][16];
#pragma unroll
    for (int b = 0; b < 2; b++)
#pragma unroll
        for (int n2 = 0; n2 < 16; n2++) {
            int n = t + 16 * b + 32 * n2;
            ar[b][n2] = __ldg(x0 + n);
            ai[b][n2] = __ldg(x1 + n);
        }

    __syncthreads();   // sM ready

    float cr[32], ci[32];

    // ======== two passes: pass 0 = forward, pass 1 = inverse (conj trick) ====
#pragma unroll
    for (int pass = 0; pass < 2; pass++) {
        // Stage 1: FFT16 over n2 for n1 = t and n1 = t+16.
        fft_dif<16>(ar[0], ai[0]);
        fft_dif<16>(ar[1], ai[1]);
        // ar[b][p] = A[n1 = t+16b][k2 = brev(p,4)]

        // Twiddle by W^{n1*k2} (running products, natural k2 order) and
        // transpose-write S[n1][k2].
        {
            float p0r = 1.0f, p0i = 0.0f, p1r = 1.0f, p1i = 0.0f;
#pragma unroll
            for (int k2 = 0; k2 < 16; k2++) {
                if (k2) {
                    float n0r = p0r * b0r - p0i * b0i;
                    float n0i = p0r * b0i + p0i * b0r;
                    p0r = n0r; p0i = n0i;
                    float n1r = p1r * b1r - p1i * b1i;
                    float n1i = p1r * b1i + p1i * b1r;
                    p1r = n1r; p1i = n1i;
                }
                int pos = brev(k2, 4);
                S[t * SROW + k2] = make_float2(
                    ar[0][pos] * p0r - ai[0][pos] * p0i,
                    ar[0][pos] * p0i + ai[0][pos] * p0r);
                S[(t + 16) * SROW + k2] = make_float2(
                    ar[1][pos] * p1r - ai[1][pos] * p1i,
                    ar[1][pos] * p1i + ai[1][pos] * p1r);
            }
        }
        __syncwarp();

        // Transpose-read: natural n1 for this thread's k2 = t.
#pragma unroll
        for (int n1 = 0; n1 < 32; n1++) {
            float2 v = S[n1 * SROW + t];
            cr[n1] = v.x;
            ci[n1] = v.y;
        }
        __syncwarp();   // buffer reusable next pass

        // Stage 2: FFT32 over n1. cr[p] = X[t + 16*brev(p,5)].
        fft_dif<32>(cr, ci);

        if (pass == 0) {
            // Spectrum multiply by real M, conjugate, and permute into the
            // stage-1 register layout for the inverse pass.
            // invIn[b][n2] = conj(M*X) at k = t + 16*(2*n2+b),
            // held in forward register p = 16*b + brev(n2,4).
#pragma unroll
            for (int b = 0; b < 2; b++)
#pragma unroll
                for (int n2 = 0; n2 < 16; n2++) {
                    int p = 16 * b + brev(n2, 4);
                    float m = sM[t + 32 * n2 + 16 * b];
                    ar[b][n2] = cr[p] * m;
                    ai[b][n2] = -ci[p] * m;
                }
        }
    }

    // y = conj(Z)/512 (1/512 folded into M): re -> row0, -im -> row1.
    float* o0 = out + row0 * NW;
    float* o1 = o0 + NW;
#pragma unroll
    for (int p = 0; p < 32; p++) {
        int m = t + 16 * brev(p, 5);
        o0[m] = cr[p];
        o1[m] = -ci[p];
    }
}

extern "C" void kernel_launch(void* const* d_in, const int* in_sizes, int n_in,
                              void* d_out, int out_size) {
    const float* x = (const float*)d_in[0];
    const float* w = (const float*)d_in[1];
    if (n_in >= 2 && in_sizes[0] < in_sizes[1]) {
        const float* t = x; x = w; w = t;
    }
    float* out = (float*)d_out;

    compute_M_kernel<<<1, NW>>>(w);

    int rows = out_size / NW;          // 16384
    int blocks = rows / (2 * NFB);     // 2048 (8 rows per block)
    fft_conv_kernel<<<blocks, THREADS>>>(x, out);
}